// round 5
// baseline (speedup 1.0000x reference)
#include <cuda_runtime.h>

// 10-qubit, 3-layer state-vector simulator. Batch S=32.
// One CTA per sample; state (1024 complex64) lives in shared memory.
// U = kron(M_0..M_9) applied as 10 single-qubit butterfly passes.
// Ring CNOT = fixed bit-twiddle permutation.
// OUTPUT: harness stores the complex64 reference coerced to float32
// (out_size==32768) => REAL PART, (32,1024) row-major.

#define NQ 10
#define DIM 1024
#define HALF 512
#define NLAYERS 3
#define NGATES (NLAYERS * NQ)   // 30

__device__ __forceinline__ float2 cfma2(float2 m0, float2 a, float2 m1, float2 b) {
    // m0*a + m1*b (complex)
    float re = fmaf(m0.x, a.x, fmaf(-m0.y, a.y, fmaf(m1.x, b.x, -m1.y * b.y)));
    float im = fmaf(m0.x, a.y, fmaf(m0.y, a.x, fmaf(m1.x, b.y,  m1.y * b.x)));
    return make_float2(re, im);
}

// RING[j] = p_{0,1}(p_{1,2}(...p_{8,9}(p_{9,0}(j))...))
// cnot_perm(c,t): if bit (9-c) of i set, flip bit (9-t). Qubit 0 = MSB (bit 9).
__device__ __forceinline__ int ring_idx(int j) {
    int idx = j;
    // pair (9,0): control bit 0, target bit 9  (applied first / innermost)
    if (idx & 1) idx ^= (1 << 9);
    // pairs (8,9), (7,8), ..., (0,1): control bit (9-p), target bit (8-p)
    #pragma unroll
    for (int p = 8; p >= 0; p--) {
        if ((idx >> (9 - p)) & 1) idx ^= (1 << (8 - p));
    }
    return idx;
}

__global__ __launch_bounds__(HALF, 2)
void statevec_kernel(const float* __restrict__ X,      // (32, 20)
                     const float* __restrict__ W,      // (3,10,3) flat 90
                     const float* __restrict__ B,      // (3,10,3) flat 90
                     float* __restrict__ out,          // (32,1024) float32 = Re(state)
                     int write_complex)                // fallback: interleaved complex64
{
    __shared__ float2 state[DIM];
    __shared__ float2 gates[NGATES][4];   // m00, m01, m10, m11

    const int s   = blockIdx.x;
    const int tid = threadIdx.x;          // 0..511

    // ---- Precompute all 30 gate matrices for this sample ----
    if (tid < NGATES) {
        const int a0 = tid * 3;           // flat angle index base: l*30 + q*3
        const float phi   = fmaf(X[s * 20 + (a0    ) % 20], W[a0    ], B[a0    ]);
        const float theta = fmaf(X[s * 20 + (a0 + 1) % 20], W[a0 + 1], B[a0 + 1]);
        const float omega = fmaf(X[s * 20 + (a0 + 2) % 20], W[a0 + 2], B[a0 + 2]);

        float st, ct;  sincosf(theta * 0.5f, &st, &ct);
        float sp, cp;  sincosf((phi + omega) * 0.5f, &sp, &cp);
        float sm, cm;  sincosf((phi - omega) * 0.5f, &sm, &cm);

        gates[tid][0] = make_float2( cp * ct, -sp * ct);   // e^{-i ppo} ct
        gates[tid][1] = make_float2(-cm * st, -sm * st);   // -e^{+i pmo} st
        gates[tid][2] = make_float2( cm * st, -sm * st);   // e^{-i pmo} st
        gates[tid][3] = make_float2( cp * ct,  sp * ct);   // e^{+i ppo} ct
    }

    // ---- Init |0...0> ----
    state[tid]        = make_float2(tid == 0 ? 1.0f : 0.0f, 0.0f);
    state[tid + HALF] = make_float2(0.0f, 0.0f);

    // Ring permutation source indices (same every layer)
    const int r0 = ring_idx(tid);
    const int r1 = ring_idx(tid + HALF);

    __syncthreads();

    #pragma unroll
    for (int l = 0; l < NLAYERS; l++) {
        // 10 single-qubit butterfly passes. Each thread owns one disjoint
        // (i0, i1) pair per pass -> no read/write hazard within a pass.
        #pragma unroll
        for (int q = 0; q < NQ; q++) {
            const int b  = 9 - q;                       // bit position for qubit q
            const int lo = tid & ((1 << b) - 1);
            const int i0 = ((tid >> b) << (b + 1)) | lo;
            const int i1 = i0 | (1 << b);

            const int g = l * NQ + q;
            const float2 m00 = gates[g][0];
            const float2 m01 = gates[g][1];
            const float2 m10 = gates[g][2];
            const float2 m11 = gates[g][3];

            const float2 a = state[i0];
            const float2 c = state[i1];
            state[i0] = cfma2(m00, a, m01, c);
            state[i1] = cfma2(m10, a, m11, c);
            __syncthreads();
        }

        // Ring CNOT permutation: new[j] = old[RING[j]] (register-staged in place)
        const float2 v0 = state[r0];
        const float2 v1 = state[r1];
        __syncthreads();
        state[tid]        = v0;
        state[tid + HALF] = v1;
        __syncthreads();
    }

    // ---- Write result ----
    if (write_complex) {
        // interleaved complex64 (only if out_size indicates room for 2 floats/elem)
        float2* o2 = (float2*)out;
        o2[s * DIM + tid]        = state[tid];
        o2[s * DIM + tid + HALF] = state[tid + HALF];
    } else {
        // float32 real part, (32,1024) row-major
        out[s * DIM + tid]        = state[tid].x;
        out[s * DIM + tid + HALF] = state[tid + HALF].x;
    }
}

extern "C" void kernel_launch(void* const* d_in, const int* in_sizes, int n_in,
                              void* d_out, int out_size) {
    // Input binding: dict insertion order from setup_inputs: [X(640), weights(90), bias(90)].
    const float* X = (const float*)d_in[0];
    const float* W = (const float*)d_in[1];
    const float* B = (const float*)d_in[2];

    // out_size==32768 (established R4): float32 output => real part of the state.
    // Defensive: if out_size were 65536 (float pairs), write interleaved complex.
    const int write_complex = (out_size >= 65536) ? 1 : 0;

    statevec_kernel<<<32, HALF>>>(X, W, B, (float*)d_out, write_complex);
}

// round 6
// speedup vs baseline: 1.2286x; 1.2286x over previous
#include <cuda_runtime.h>

// 10-qubit, 3-layer state-vector simulator. Batch S=32.
// One CTA per sample, 256 threads, 4 amplitudes/thread, 2 qubits per pass
// (gates within a layer commute) -> 5 passes/layer, 15 barriers total.
// Ring-CNOT permutation is GF(2)-linear: folded into next-pass gather /
// final output scatter. Output = float32 REAL PART, (32,1024) row-major.

#define DIM 1024
#define NT 256
#define NLAYERS 3
#define NGATES 30

__device__ __forceinline__ float2 cfma2(float2 m0, float2 a, float2 m1, float2 b) {
    float re = fmaf(m0.x, a.x, fmaf(-m0.y, a.y, fmaf(m1.x, b.x, -m1.y * b.y)));
    float im = fmaf(m0.x, a.y, fmaf(m0.y, a.x, fmaf(m1.x, b.y,  m1.y * b.x)));
    return make_float2(re, im);
}

// smem bank-spread swizzle (bijective, linear)
__device__ __forceinline__ int phys_idx(int j) { return j ^ ((j >> 5) & 31); }

// RING[j] = p01(p12(...(p89(p90(j))...))) ; linear over GF(2), ring(0)=0.
__host__ __device__ constexpr int ring_c(int j) {
    int idx = j;
    if (idx & 1) idx ^= (1 << 9);                 // pair (9,0) first
    for (int p = 8; p >= 0; p--)
        if ((idx >> (9 - p)) & 1) idx ^= (1 << (8 - p));
    return idx;
}
// RING^{-1}: apply p01, p12, ..., p89, then p90 (each an involution)
__device__ __forceinline__ int ring_inv(int i) {
    int idx = i;
    #pragma unroll
    for (int b = 9; b >= 1; b--)
        if ((idx >> b) & 1) idx ^= (1 << (b - 1));
    if (idx & 1) idx ^= (1 << 9);
    return idx;
}

// One pass: qubit bits (BL+1, BL). MODE 0: synth |0..0>, 1: plain gather,
// 2: gather through RING (consumes previous layer's permutation).
// LAST: scatter real part to gmem through RING^{-1} instead of smem store.
template<int BL, int MODE, bool LAST>
__device__ __forceinline__ void do_pass(float2* st, const float2 (*gates)[4],
                                        int l, int t, float* out)
{
    const int jbase = ((t >> BL) << (BL + 2)) | (t & ((1 << BL) - 1));
    const int rbase = (MODE == 2) ? ring_c(jbase) : 0;

    float2 a[4];
    #pragma unroll
    for (int k = 0; k < 4; k++) {
        const int j = jbase | (k << BL);
        if (MODE == 0) {
            a[k] = make_float2(j == 0 ? 1.0f : 0.0f, 0.0f);
        } else if (MODE == 1) {
            a[k] = st[phys_idx(j)];
        } else {
            const int src = rbase ^ ring_c(k << BL);   // ring_c(k<<BL) folds to const
            a[k] = st[phys_idx(src)];
        }
    }

    // gate on high bit (BL+1): qubit 9-(BL+1) -> pairs (a0,a2),(a1,a3)
    {
        const int g = l * 10 + (8 - BL);
        const float2 m00 = gates[g][0], m01 = gates[g][1];
        const float2 m10 = gates[g][2], m11 = gates[g][3];
        float2 n0 = cfma2(m00, a[0], m01, a[2]);
        float2 n2 = cfma2(m10, a[0], m11, a[2]);
        float2 n1 = cfma2(m00, a[1], m01, a[3]);
        float2 n3 = cfma2(m10, a[1], m11, a[3]);
        a[0] = n0; a[1] = n1; a[2] = n2; a[3] = n3;
    }
    // gate on low bit (BL): qubit 9-BL -> pairs (a0,a1),(a2,a3)
    {
        const int g = l * 10 + (9 - BL);
        const float2 m00 = gates[g][0], m01 = gates[g][1];
        const float2 m10 = gates[g][2], m11 = gates[g][3];
        float2 n0 = cfma2(m00, a[0], m01, a[1]);
        float2 n1 = cfma2(m10, a[0], m11, a[1]);
        float2 n2 = cfma2(m00, a[2], m01, a[3]);
        float2 n3 = cfma2(m10, a[2], m11, a[3]);
        a[0] = n0; a[1] = n1; a[2] = n2; a[3] = n3;
    }

    #pragma unroll
    for (int k = 0; k < 4; k++) {
        const int j = jbase | (k << BL);
        if (LAST) out[ring_inv(j)] = a[k].x;       // final perm + real part
        else      st[phys_idx(j)] = a[k];
    }
}

__global__ __launch_bounds__(NT, 2)
void statevec_kernel(const float* __restrict__ X,      // (32, 20)
                     const float* __restrict__ W,      // 90
                     const float* __restrict__ B,      // 90
                     float* __restrict__ out)          // (32,1024) f32 = Re(state)
{
    __shared__ float2 st[DIM];
    __shared__ float2 gates[NGATES][4];

    const int s = blockIdx.x;
    const int t = threadIdx.x;

    if (t < NGATES) {
        const int a0 = t * 3;
        const float phi   = fmaf(X[s * 20 + (a0    ) % 20], W[a0    ], B[a0    ]);
        const float theta = fmaf(X[s * 20 + (a0 + 1) % 20], W[a0 + 1], B[a0 + 1]);
        const float omega = fmaf(X[s * 20 + (a0 + 2) % 20], W[a0 + 2], B[a0 + 2]);

        float stq, ctq;  __sincosf(theta * 0.5f, &stq, &ctq);
        float sp,  cp;   __sincosf((phi + omega) * 0.5f, &sp, &cp);
        float sm,  cm;   __sincosf((phi - omega) * 0.5f, &sm, &cm);

        gates[t][0] = make_float2( cp * ctq, -sp * ctq);
        gates[t][1] = make_float2(-cm * stq, -sm * stq);
        gates[t][2] = make_float2( cm * stq, -sm * stq);
        gates[t][3] = make_float2( cp * ctq,  sp * ctq);
    }
    __syncthreads();

    float* o = out + s * DIM;

    // layer 0 (first pass synthesizes |0...0>)
    do_pass<8, 0, false>(st, gates, 0, t, o); __syncthreads();
    do_pass<6, 1, false>(st, gates, 0, t, o); __syncthreads();
    do_pass<4, 1, false>(st, gates, 0, t, o); __syncthreads();
    do_pass<2, 1, false>(st, gates, 0, t, o); __syncthreads();
    do_pass<0, 1, false>(st, gates, 0, t, o); __syncthreads();
    // layer 1 (gather applies layer-0 ring perm)
    do_pass<8, 2, false>(st, gates, 1, t, o); __syncthreads();
    do_pass<6, 1, false>(st, gates, 1, t, o); __syncthreads();
    do_pass<4, 1, false>(st, gates, 1, t, o); __syncthreads();
    do_pass<2, 1, false>(st, gates, 1, t, o); __syncthreads();
    do_pass<0, 1, false>(st, gates, 1, t, o); __syncthreads();
    // layer 2 (gather applies layer-1 ring perm; last pass scatters to gmem
    // through RING^{-1}, applying layer-2's perm)
    do_pass<8, 2, false>(st, gates, 2, t, o); __syncthreads();
    do_pass<6, 1, false>(st, gates, 2, t, o); __syncthreads();
    do_pass<4, 1, false>(st, gates, 2, t, o); __syncthreads();
    do_pass<2, 1, false>(st, gates, 2, t, o); __syncthreads();
    do_pass<0, 1, true >(st, gates, 2, t, o);
}

extern "C" void kernel_launch(void* const* d_in, const int* in_sizes, int n_in,
                              void* d_out, int out_size) {
    const float* X = (const float*)d_in[0];   // (32,20)
    const float* W = (const float*)d_in[1];   // 90
    const float* B = (const float*)d_in[2];   // 90
    statevec_kernel<<<32, NT>>>(X, W, B, (float*)d_out);
}

// round 7
// speedup vs baseline: 1.2555x; 1.0219x over previous
#include <cuda_runtime.h>

// 10-qubit, 3-layer state-vector sim, batch 32. One CTA/sample, 256 thr, 4 amps/thr.
// Layout A: j = [w2 w1 w0 | l4..l0 | k1 k0]  (thread = w,l ; regs = k)
//   alpha pass: qubits 8,9 (reg bits b1,b0) + qubits 3..7 (lane bits, shfl) -> 7 gates, 0 barriers
// Layout B: j = [k1 k0 | l4..l0 | w2 w1 w0]
//   beta pass: qubits 0,1 (reg bits b9,b8) + qubit 2 (lane bit l4, shfl) -> 3 gates
// Ring-CNOT perm is GF(2)-linear; folded into B->A gathers and the final store.
// Output: float32 real part, (32,1024) row-major.

#define NT 256
#define DIM 1024
#define NGATES 30

__device__ __forceinline__ float2 cmulc(float2 a, float2 b) {
    return make_float2(a.x * b.x - a.y * b.y, a.x * b.y + a.y * b.x);
}
__device__ __forceinline__ float2 cfma2(float2 m0, float2 a, float2 m1, float2 b) {
    float re = fmaf(m0.x, a.x, fmaf(-m0.y, a.y, fmaf(m1.x, b.x, -m1.y * b.y)));
    float im = fmaf(m0.x, a.y, fmaf(m0.y, a.x, fmaf(m1.x, b.y,  m1.y * b.x)));
    return make_float2(re, im);
}

// ring(j): bit_i' = b_i^b_{i+1} (i=0..7), b8' = b8^b9^b0, b9' = b9^b0
__device__ __forceinline__ int ring_f(int j) {
    int low = (j ^ (j >> 1)) & 0xFF;
    int b8  = ((j >> 8) ^ (j >> 9) ^ j) & 1;
    int b9  = ((j >> 9) ^ j) & 1;
    return low | (b8 << 8) | (b9 << 9);
}
// ring^{-1}: apply p01,p12,...,p89 then p90
__device__ __forceinline__ int ring_inv(int i) {
    int idx = i;
    #pragma unroll
    for (int b = 9; b >= 1; b--)
        if ((idx >> b) & 1) idx ^= (1 << (b - 1));
    if (idx & 1) idx ^= (1 << 9);
    return idx;
}

__device__ __forceinline__ int phys(int j) { return j ^ ((j >> 3) & 15); }

// butterfly on reg-bit pairing (0,2)(1,3)
__device__ __forceinline__ void bf_hi(float2 a[4], const float2* g) {
    float2 m00 = g[0], m01 = g[1], m10 = g[2], m11 = g[3];
    float2 n0 = cfma2(m00, a[0], m01, a[2]);
    float2 n2 = cfma2(m10, a[0], m11, a[2]);
    float2 n1 = cfma2(m00, a[1], m01, a[3]);
    float2 n3 = cfma2(m10, a[1], m11, a[3]);
    a[0] = n0; a[1] = n1; a[2] = n2; a[3] = n3;
}
// butterfly on reg-bit pairing (0,1)(2,3)
__device__ __forceinline__ void bf_lo(float2 a[4], const float2* g) {
    float2 m00 = g[0], m01 = g[1], m10 = g[2], m11 = g[3];
    float2 n0 = cfma2(m00, a[0], m01, a[1]);
    float2 n1 = cfma2(m10, a[0], m11, a[1]);
    float2 n2 = cfma2(m00, a[2], m01, a[3]);
    float2 n3 = cfma2(m10, a[2], m11, a[3]);
    a[0] = n0; a[1] = n1; a[2] = n2; a[3] = n3;
}
// butterfly across lane bit lb via shfl.xor
__device__ __forceinline__ void bf_shfl(float2 a[4], const float2* g, int lane, int lb) {
    const int msk = 1 << lb;
    const bool hi = (lane >> lb) & 1;
    const float2 cA = hi ? g[3] : g[0];   // coeff of own amp
    const float2 cB = hi ? g[2] : g[1];   // coeff of partner amp
    #pragma unroll
    for (int k = 0; k < 4; k++) {
        float2 o;
        o.x = __shfl_xor_sync(0xffffffffu, a[k].x, msk);
        o.y = __shfl_xor_sync(0xffffffffu, a[k].y, msk);
        a[k] = cfma2(cA, a[k], cB, o);
    }
}

__global__ __launch_bounds__(NT, 2)
void statevec_kernel(const float* __restrict__ X,      // (32,20)
                     const float* __restrict__ W,      // 90
                     const float* __restrict__ B,      // 90
                     float* __restrict__ out)          // (32,1024) f32 = Re(state)
{
    __shared__ float2 buf0[DIM];
    __shared__ float2 buf1[DIM];
    __shared__ float2 gates[NGATES][4];   // m00,m01,m10,m11

    const int s    = blockIdx.x;
    const int t    = threadIdx.x;
    const int lane = t & 31;
    const int w    = t >> 5;

    if (t < NGATES) {
        const int a0 = t * 3;
        const float phi   = fmaf(X[s * 20 + (a0    ) % 20], W[a0    ], B[a0    ]);
        const float theta = fmaf(X[s * 20 + (a0 + 1) % 20], W[a0 + 1], B[a0 + 1]);
        const float omega = fmaf(X[s * 20 + (a0 + 2) % 20], W[a0 + 2], B[a0 + 2]);

        float stq, ctq;  __sincosf(theta * 0.5f, &stq, &ctq);
        float sp,  cp;   __sincosf((phi + omega) * 0.5f, &sp, &cp);
        float sm,  cm;   __sincosf((phi - omega) * 0.5f, &sm, &cm);

        gates[t][0] = make_float2( cp * ctq, -sp * ctq);
        gates[t][1] = make_float2(-cm * stq, -sm * stq);
        gates[t][2] = make_float2( cm * stq, -sm * stq);
        gates[t][3] = make_float2( cp * ctq,  sp * ctq);
    }
    __syncthreads();                                       // bar 1

    float2 a[4];

    // ---- layer 0 alpha on |0...0>: closed-form product (only w==0 nonzero) ----
    if (w == 0) {
        float2 c = make_float2(1.0f, 0.0f);
        #pragma unroll
        for (int lb = 0; lb < 5; lb++) {                   // lane bit lb -> qubit 7-lb
            const int bit = (lane >> lb) & 1;
            c = cmulc(c, gates[7 - lb][bit ? 2 : 0]);      // column-0 entry
        }
        #pragma unroll
        for (int k = 0; k < 4; k++) {
            float2 v = cmulc(c, gates[8][(k >> 1) ? 2 : 0]);  // qubit 8 on b1
            a[k] = cmulc(v, gates[9][(k & 1) ? 2 : 0]);       // qubit 9 on b0
        }
    } else {
        #pragma unroll
        for (int k = 0; k < 4; k++) a[k] = make_float2(0.0f, 0.0f);
    }

    #pragma unroll
    for (int l = 0; l < 3; l++) {
        const float2* G = gates[0] + l * 10 * 4 / 4;       // &gates[l*10][0]
        const float2 (*Gl)[4] = (const float2 (*)[4])&gates[l * 10];

        if (l > 0) {
            // gather layout A through ring (consumes previous layer's perm)
            #pragma unroll
            for (int k = 0; k < 4; k++) {
                const int jA = (w << 7) | (lane << 2) | k;
                a[k] = buf1[phys(ring_f(jA))];
            }
            // alpha: qubits 8,9 on reg bits; 3..7 on lane bits
            bf_hi(a, Gl[8]);                               // b1 -> qubit 8
            bf_lo(a, Gl[9]);                               // b0 -> qubit 9
            #pragma unroll
            for (int lb = 0; lb < 5; lb++)
                bf_shfl(a, Gl[7 - lb], lane, lb);
        }
        (void)G;

        // exchange A -> B
        #pragma unroll
        for (int k = 0; k < 4; k++)
            buf0[phys((w << 7) | (lane << 2) | k)] = a[k];
        __syncthreads();                                   // bars 2,4,6
        #pragma unroll
        for (int k = 0; k < 4; k++)
            a[k] = buf0[phys((k << 8) | (lane << 3) | w)];

        // beta: qubits 0,1 on reg bits b9,b8; qubit 2 on lane bit l4
        bf_hi(a, Gl[0]);                                   // b9 -> qubit 0
        bf_lo(a, Gl[1]);                                   // b8 -> qubit 1
        bf_shfl(a, Gl[2], lane, 4);                        // b7 -> qubit 2

        if (l < 2) {
            // store layout B for next layer's ring-composed gather
            #pragma unroll
            for (int k = 0; k < 4; k++)
                buf1[phys((k << 8) | (lane << 3) | w)] = a[k];
            __syncthreads();                               // bars 3,5
        }
    }

    // ---- final: apply layer-2 ring perm via inverse scatter; real part ----
    float* o = out + s * DIM;
    #pragma unroll
    for (int k = 0; k < 4; k++) {
        const int jB = (k << 8) | (lane << 3) | w;
        o[ring_inv(jB)] = a[k].x;
    }
}

extern "C" void kernel_launch(void* const* d_in, const int* in_sizes, int n_in,
                              void* d_out, int out_size) {
    const float* X = (const float*)d_in[0];   // (32,20)
    const float* W = (const float*)d_in[1];   // 90
    const float* B = (const float*)d_in[2];   // 90
    statevec_kernel<<<32, NT>>>(X, W, B, (float*)d_out);
}